// round 1
// baseline (speedup 1.0000x reference)
#include <cuda_runtime.h>

// SE block: x [32,256,56,56] f32 -> GAP -> FC(256->32)+ReLU -> FC(32->256)+sigmoid -> x*g
// HW = 56*56 = 3136 floats = 784 float4 per (b,c) plane. B*C = 8192 planes.

#define B 32
#define C 256
#define BOT 32
#define HW 3136
#define HW4 784
#define BC (B * C)

__device__ float d_s[BC];   // pooled means
__device__ float d_g[BC];   // gates

__global__ void __launch_bounds__(256) se_reduce_kernel(const float* __restrict__ x) {
    const int bc = blockIdx.x;
    const float4* __restrict__ xp =
        reinterpret_cast<const float4*>(x + (size_t)bc * HW);
    float sum = 0.0f;
    #pragma unroll 4
    for (int i = threadIdx.x; i < HW4; i += 256) {
        float4 v = xp[i];
        sum += (v.x + v.y) + (v.z + v.w);
    }
    // warp reduce
    #pragma unroll
    for (int o = 16; o > 0; o >>= 1)
        sum += __shfl_xor_sync(0xffffffffu, sum, o);
    __shared__ float ws[8];
    if ((threadIdx.x & 31) == 0) ws[threadIdx.x >> 5] = sum;
    __syncthreads();
    if (threadIdx.x < 8) {
        float v = ws[threadIdx.x];
        #pragma unroll
        for (int o = 4; o > 0; o >>= 1)
            v += __shfl_xor_sync(0xffu, v, o);
        if (threadIdx.x == 0) d_s[bc] = v * (1.0f / (float)HW);
    }
}

__global__ void __launch_bounds__(1024) se_mlp_kernel(const float* __restrict__ w1,
                                                      const float* __restrict__ b1,
                                                      const float* __restrict__ w2,
                                                      const float* __restrict__ b2) {
    __shared__ float sh_s[BC];       // 32 KB
    __shared__ float sh_h[B * BOT];  // 4 KB
    const int tid = threadIdx.x;

    for (int i = tid; i < BC; i += 1024) sh_s[i] = d_s[i];
    __syncthreads();

    // hidden: h[b][o] = relu(dot(s[b,:], w1[o,:]) + b1[o]) — exactly 1024 outputs
    {
        const int b = tid >> 5;       // 0..31
        const int o = tid & 31;       // 0..31
        float acc = b1[o];
        const float* __restrict__ srow = sh_s + b * C;
        const float* __restrict__ wrow = w1 + o * C;
        #pragma unroll 8
        for (int c = 0; c < C; c++) acc = fmaf(srow[c], wrow[c], acc);
        sh_h[b * BOT + o] = fmaxf(acc, 0.0f);
    }
    __syncthreads();

    // gate: g[b][c] = sigmoid(dot(h[b,:], w2[c,:]) + b2[c]) — 8192 outputs
    for (int i = tid; i < BC; i += 1024) {
        const int b = i >> 8;         // 0..31
        const int c = i & 255;        // 0..255
        float acc = b2[c];
        const float* __restrict__ hrow = sh_h + b * BOT;
        const float* __restrict__ wrow = w2 + c * BOT;
        #pragma unroll
        for (int o = 0; o < BOT; o++) acc = fmaf(hrow[o], wrow[o], acc);
        d_g[i] = 1.0f / (1.0f + __expf(-acc));
    }
}

__global__ void __launch_bounds__(256) se_scale_kernel(const float* __restrict__ x,
                                                       float* __restrict__ out) {
    const int bc = blockIdx.x;
    const float g = d_g[bc];
    const float4* __restrict__ xp =
        reinterpret_cast<const float4*>(x + (size_t)bc * HW);
    float4* __restrict__ op = reinterpret_cast<float4*>(out + (size_t)bc * HW);
    #pragma unroll 4
    for (int i = threadIdx.x; i < HW4; i += 256) {
        float4 v = xp[i];
        v.x *= g; v.y *= g; v.z *= g; v.w *= g;
        op[i] = v;
    }
}

extern "C" void kernel_launch(void* const* d_in, const int* in_sizes, int n_in,
                              void* d_out, int out_size) {
    const float* x  = (const float*)d_in[0];
    const float* w1 = (const float*)d_in[1];
    const float* b1 = (const float*)d_in[2];
    const float* w2 = (const float*)d_in[3];
    const float* b2 = (const float*)d_in[4];
    float* out = (float*)d_out;

    se_reduce_kernel<<<BC, 256>>>(x);
    se_mlp_kernel<<<1, 1024>>>(w1, b1, w2, b2);
    se_scale_kernel<<<BC, 256>>>(x, out);
}

// round 2
// speedup vs baseline: 3.5037x; 3.5037x over previous
#include <cuda_runtime.h>

// SE block fused into ONE persistent kernel with a software grid barrier.
// x [32,256,56,56] f32. HW=3136 (=784 float4). B*C=8192 planes.
// 128 blocks x 1024 threads, 64 planes/block; each block's 64 planes share one
// batch index b, so it can compute its own hidden vector + gates after the
// barrier (redundant across the 4 blocks per b, but ~8KFLOP => free).

#define C        256
#define BOT      32
#define HW       3136
#define HW4      784
#define BC       8192
#define GRID     128
#define PPB      64          // planes per block = BC/GRID
#define NTHREADS 1024

__device__ float d_s[BC];                       // pooled means
__device__ unsigned int d_arrive = 0;           // barrier arrival counter
__device__ volatile unsigned int d_gen = 0;     // barrier generation

__global__ void __launch_bounds__(NTHREADS, 1) se_fused_kernel(
    const float* __restrict__ x,
    const float* __restrict__ w1, const float* __restrict__ b1,
    const float* __restrict__ w2, const float* __restrict__ b2,
    float* __restrict__ out)
{
    const int tid  = threadIdx.x;
    const int warp = tid >> 5;
    const int lane = tid & 31;
    const int bid  = blockIdx.x;
    const int plane0 = bid * PPB;

    // ---------------- Phase 1: pooled sums (2 planes per warp) ----------------
    #pragma unroll
    for (int p = 0; p < 2; p++) {
        const int plane = plane0 + warp + p * 32;
        const float4* __restrict__ xp =
            reinterpret_cast<const float4*>(x) + (size_t)plane * HW4;
        float sum = 0.0f;
        #pragma unroll 5
        for (int i = lane; i < HW4; i += 32) {
            float4 v = xp[i];
            sum += (v.x + v.y) + (v.z + v.w);
        }
        #pragma unroll
        for (int o = 16; o > 0; o >>= 1)
            sum += __shfl_xor_sync(0xffffffffu, sum, o);
        if (lane == 0) d_s[plane] = sum * (1.0f / (float)HW);
    }

    // ---------------- Grid barrier (replay-safe generation scheme) ------------
    __threadfence();     // make this thread's d_s writes globally visible
    __syncthreads();
    if (tid == 0) {
        const unsigned int target = d_gen;   // read BEFORE arriving: stable
        const unsigned int old = atomicAdd(&d_arrive, 1);
        if (old == GRID - 1) {
            d_arrive = 0;                    // reset for next replay
            __threadfence();
            d_gen = target + 1;              // release
        } else {
            while (d_gen == target) __nanosleep(64);
        }
        __threadfence();                     // acquire
    }
    __syncthreads();

    // ---------------- Phase 2: MLP (per-block, redundant per b) ---------------
    __shared__ float sh_h[BOT];
    __shared__ float sh_g[PPB];
    const int b = plane0 >> 8;               // batch index for all our planes

    {   // hidden: warp o computes h[o] = relu(dot(s[b,:], w1[o,:]) + b1[o])
        const int o = warp;                  // 32 warps -> 32 hidden units
        float partial = 0.0f;
        #pragma unroll
        for (int k = 0; k < 8; k++) {
            const int c = lane + k * 32;
            partial = fmaf(d_s[b * C + c], w1[o * C + c], partial);
        }
        #pragma unroll
        for (int off = 16; off > 0; off >>= 1)
            partial += __shfl_xor_sync(0xffffffffu, partial, off);
        if (lane == 0) sh_h[o] = fmaxf(partial + b1[o], 0.0f);
    }
    __syncthreads();

    if (tid < PPB) {                         // 64 gates for our c-range
        const int c = (plane0 & 255) + tid;
        float acc = b2[c];
        #pragma unroll
        for (int o = 0; o < BOT; o++)
            acc = fmaf(sh_h[o], w2[c * BOT + o], acc);
        sh_g[tid] = 1.0f / (1.0f + __expf(-acc));
    }
    __syncthreads();

    // ---------------- Phase 3: scale (same planes -> L2-warm reads) -----------
    #pragma unroll
    for (int p = 0; p < 2; p++) {
        const int j = warp + p * 32;
        const int plane = plane0 + j;
        const float g = sh_g[j];
        const float4* __restrict__ xp =
            reinterpret_cast<const float4*>(x) + (size_t)plane * HW4;
        float4* __restrict__ op =
            reinterpret_cast<float4*>(out) + (size_t)plane * HW4;
        #pragma unroll 5
        for (int i = lane; i < HW4; i += 32) {
            float4 v = xp[i];
            v.x *= g; v.y *= g; v.z *= g; v.w *= g;
            op[i] = v;
        }
    }
}

extern "C" void kernel_launch(void* const* d_in, const int* in_sizes, int n_in,
                              void* d_out, int out_size) {
    const float* x  = (const float*)d_in[0];
    const float* w1 = (const float*)d_in[1];
    const float* b1 = (const float*)d_in[2];
    const float* w2 = (const float*)d_in[3];
    const float* b2 = (const float*)d_in[4];
    float* out = (float*)d_out;

    se_fused_kernel<<<GRID, NTHREADS>>>(x, w1, b1, w2, b2, out);
}